// round 17
// baseline (speedup 1.0000x reference)
#include <cuda_runtime.h>
#include <cuda_bf16.h>
#include <math.h>
#include <stdint.h>

#define N_PTS   8192
#define D_DIM   8
#define K_DIM   64
#define Q_DIM   16
#define KQ      1024
#define TWO_PI  6.283185307179586f

#define EPHI_SZ (N_PTS * KQ)    // 8388608
#define G_SZ    (KQ * KQ)       // 1048576
// d_out layout: [E_phi (N,KQ) | G (KQ,KQ) | E_cos_sq (N,KQ)]

// -------- device scratch --------
__device__ float g_dpart[256 * KQ];
__device__ __nv_bfloat16 g_hi[(size_t)KQ * N_PTS];
__device__ __nv_bfloat16 g_lo[(size_t)KQ * N_PTS];

// ---------------------------------------------------------------------------
// helpers
// ---------------------------------------------------------------------------
__device__ __forceinline__ uint32_t smem_u32(const void* p) {
    uint32_t a;
    asm("{ .reg .u64 t; cvta.to.shared.u64 t, %1; cvt.u32.u64 %0, t; }"
        : "=r"(a) : "l"(p));
    return a;
}
__device__ __forceinline__ void cp16(uint32_t dst, const void* src) {
    asm volatile("cp.async.cg.shared.global [%0], [%1], 16;"
                 :: "r"(dst), "l"(src));
}
__device__ __forceinline__ void cp_commit() {
    asm volatile("cp.async.commit_group;" ::: "memory");
}
template <int N>
__device__ __forceinline__ void cp_wait() {
    asm volatile("cp.async.wait_group %0;" :: "n"(N) : "memory");
}
__device__ __forceinline__ void bar_sync(int id, int cnt) {
    asm volatile("bar.sync %0, %1;" :: "r"(id), "r"(cnt) : "memory");
}
__device__ __forceinline__ void ldsm4(uint32_t* r, uint32_t addr) {
    asm volatile("ldmatrix.sync.aligned.m8n8.x4.shared.b16 {%0,%1,%2,%3}, [%4];"
                 : "=r"(r[0]), "=r"(r[1]), "=r"(r[2]), "=r"(r[3]) : "r"(addr));
}
__device__ __forceinline__ void mma_bf16(float* c, const uint32_t* a,
                                         uint32_t b0, uint32_t b1) {
    asm volatile(
        "mma.sync.aligned.m16n8k16.row.col.f32.bf16.bf16.f32 "
        "{%0,%1,%2,%3}, {%4,%5,%6,%7}, {%8,%9}, {%0,%1,%2,%3};"
        : "+f"(c[0]), "+f"(c[1]), "+f"(c[2]), "+f"(c[3])
        : "r"(a[0]), "r"(a[1]), "r"(a[2]), "r"(a[3]), "r"(b0), "r"(b1));
}

// swizzled offset within a 64B-row buffer (16B granules)
__device__ __forceinline__ uint32_t swz(int row, int seg) {
    return (uint32_t)(row * 64 + ((seg ^ ((row >> 1) & 3)) << 4));
}

// ---------------------------------------------------------------------------
// Kernel 1: fused E_phi, E_cos_sq, split-bf16 transposed hi/lo, diag partials.
// Strength-reduced inner loop (R16-proven, ~24us).
// ---------------------------------------------------------------------------
__global__ void __launch_bounds__(256) ephi_kernel(const float* __restrict__ X,
                            const float* __restrict__ z,
                            const float* __restrict__ weight,
                            const float* __restrict__ mu,
                            const float* __restrict__ stdv,
                            const float* __restrict__ alpha,
                            const float* __restrict__ var_mu_w,
                            const float* __restrict__ var_sigma_w,
                            float* __restrict__ out)
{
    const int tid = threadIdx.x;
    const int kq0 = blockIdx.x * 256;
    const int kq  = kq0 + tid;
    const int n0  = blockIdx.y * 32;

    __shared__ float Xs[256];                  // 2*pi*x
    __shared__ float Xs2[256];                 // (2*pi*x)^2
    __shared__ float s_mp[128], s_sp[128];
    __shared__ __nv_bfloat16 s_hi[256][34];
    __shared__ __nv_bfloat16 s_lo[256][34];

    {
        float xv = TWO_PI * X[n0 * D_DIM + tid];
        Xs[tid]  = xv;
        Xs2[tid] = xv * xv;
    }
    if (tid < 128) {
        s_mp[tid] = 1.0f / (mu[tid] + 1e-8f);
        s_sp[tid] = 1.0f / (TWO_PI * stdv[tid] + 1e-8f);
    }
    __syncthreads();

    const int q = kq & (Q_DIM - 1);
    float ew[D_DIM], cc[D_DIM], czn[D_DIM];
    float pc = 0.0f, c2 = 0.0f;
#pragma unroll
    for (int d = 0; d < D_DIM; ++d) {
        const float mp = s_mp[d * Q_DIM + q];
        const float sp = s_sp[d * Q_DIM + q];
        const float e  = mp + sp * var_mu_w[d * KQ + kq];
        const float c  = sp * sp * var_sigma_w[d * KQ + kq];
        const float zv = TWO_PI * z[d * KQ + kq];
        ew[d]  = e;
        cc[d]  = c;
        czn[d] = -2.0f * c * zv;
        pc     = fmaf(e, zv, pc);
        c2     = fmaf(c, zv * zv, c2);
    }
    const float a    = alpha[kq];
    const float coef = 2.0f * weight[q] * (1.0f / (float)K_DIM);
    const float sq   = sqrtf(coef);
    const float amp  = a - pc;

    float* __restrict__ outE = out;
    float* __restrict__ outC = out + EPHI_SZ + G_SZ;

    float dsum = 0.0f;
#pragma unroll 4
    for (int r = 0; r < 32; ++r) {
        float phase = amp, s = c2;
#pragma unroll
        for (int d = 0; d < D_DIM; ++d) {
            const float xv  = Xs [r * D_DIM + d];
            const float xv2 = Xs2[r * D_DIM + d];
            phase = fmaf(ew[d],  xv,  phase);
            s     = fmaf(cc[d],  xv2, s);
            s     = fmaf(czn[d], xv,  s);
        }
        float cw    = __cosf(phase);
        float decay = __expf(-0.5f * s);

        const int n = n0 + r;
        float E = sq * decay * cw;
        outE[n * KQ + kq] = E;

        float d2  = decay * decay;
        float d4  = d2 * d2;
        float c2w = 2.0f * cw * cw - 1.0f;
        float ecs = coef * (0.5f + 0.5f * d4 * c2w);
        outC[n * KQ + kq] = ecs;
        dsum += ecs;

        __nv_bfloat16 h = __float2bfloat16(E);
        s_hi[tid][r] = h;
        s_lo[tid][r] = __float2bfloat16(E - __bfloat162float(h));
    }
    g_dpart[blockIdx.y * KQ + kq] = dsum;
    __syncthreads();

    uint32_t* __restrict__ H = (uint32_t*)g_hi;
    uint32_t* __restrict__ L = (uint32_t*)g_lo;
#pragma unroll
    for (int i = 0; i < 16; ++i) {
        int v   = tid + i * 256;
        int row = v >> 4;
        int seg = v & 15;
        uint32_t h2 = *(const uint32_t*)&s_hi[row][seg * 2];
        uint32_t l2 = *(const uint32_t*)&s_lo[row][seg * 2];
        size_t o = ((size_t)(kq0 + row) * N_PTS + n0) / 2 + seg;
        H[o] = h2;
        L[o] = l2;
    }
}

// ---------------------------------------------------------------------------
// Kernel 2: SYRK — pair-shared B with 3-STAGE rotation (single barrier/iter).
// 136 upper-triangular 64x64 tiles, 256 threads = 8 warps.
// Warp (ms, kset): ms = m-half (32 rows), kset = k-quarter (32 of 128 per sc).
// A: warp-private, 2 stages x (AHI 2KB | ALO 2KB) = 8KB/warp (64KB total).
// B: SHARED per kset pair, 3 stages x (BHI 4KB | BLO 4KB) = 24KB/kset (96KB).
// Per sc: cp_wait<1>; bar(pair) [partner's half visible AND partner done
// reading stage (sc+2)%3 at its iter sc-1]; B-refill into (sc+2)%3 (overlaps
// ldsm head); batched ldsm; A-refill (own stage, own reads done); commit;
// hh/hl/lh chains. Total smem 160KB.
// Epilogue: 4-set smem reduce + write/mirror; diagonal tiles reduce g_dpart.
// ---------------------------------------------------------------------------
#define A_STAGE  4096                 // AHI 2048 | ALO 2048
#define A_WBUF   (2 * A_STAGE)        // 8192 per warp
#define B_REGION (8 * A_WBUF)         // 65536: B region base
#define B_STAGE  8192                 // BHI 4096 | BLO 4096
#define B_KBUF   (3 * B_STAGE)        // 24576 per kset (3 stages)
#define SMEM_SYRK (B_REGION + 4 * B_KBUF)   // 163840
#define NSC 64
#define RED_STRIDE 65
#define RED_BYTES (64 * RED_STRIDE * 4)   // 16640
#define SDIAG_OFF (3 * RED_BYTES)         // 49920

// A refill: 32 rows x 32k, hi+lo = 256 16B-chunks (8 cp per lane)
__device__ __forceinline__ void load_A(uint32_t astage, int i0r,
                                       size_t koff, int lane)
{
#pragma unroll
    for (int it = 0; it < 8; ++it) {
        int cid = it * 32 + lane;
        int h   = cid >> 7;
        int rc  = cid & 127;
        int row = rc >> 2;
        int seg = rc & 3;
        uint32_t dst = astage + (uint32_t)(h ? 2048 : 0) + swz(row, seg);
        const __nv_bfloat16* base = h ? g_lo : g_hi;
        cp16(dst, (const char*)(base + (size_t)(i0r + row) * N_PTS + koff) + seg * 16);
    }
}
// B-half refill: 32 rows (ms half) x 32k, hi+lo = 256 chunks (8 cp per lane)
__device__ __forceinline__ void load_Bhalf(uint32_t bstage, int j0, int ms,
                                           size_t koff, int lane)
{
#pragma unroll
    for (int it = 0; it < 8; ++it) {
        int cid = it * 32 + lane;
        int h   = cid >> 7;
        int rc  = cid & 127;
        int row = (rc >> 2) + ms * 32;
        int seg = rc & 3;
        uint32_t dst = bstage + (uint32_t)(h ? 4096 : 0) + swz(row, seg);
        const __nv_bfloat16* base = h ? g_lo : g_hi;
        cp16(dst, (const char*)(base + (size_t)(j0 + row) * N_PTS + koff) + seg * 16);
    }
}

__global__ void __launch_bounds__(256, 1) syrk_mma_kernel(float* __restrict__ out)
{
    extern __shared__ __align__(1024) char smem[];
    const uint32_t sbase = smem_u32(smem);
    const int tid  = threadIdx.x;
    const int lane = tid & 31;
    const int wid  = tid >> 5;
    const int ms   = wid & 1;               // m-half
    const int kset = wid >> 1;              // k-quarter
    const int wm   = ms * 32;
    const int barid = 1 + kset;             // named barrier per pair
    const uint32_t abase = sbase + (uint32_t)wid * A_WBUF;
    const uint32_t bbase = sbase + B_REGION + (uint32_t)kset * B_KBUF;

    int b = blockIdx.x, ti = 0, rem = b;
    while (rem >= 16 - ti) { rem -= 16 - ti; ++ti; }
    const int tj = ti + rem;
    const int i0 = ti * 64;
    const int j0 = tj * 64;
    const int i0r = i0 + wm;
    const bool diagTile = (ti == tj);

    // ldmatrix addresses
    const int g  = lane >> 3;
    const int rr = lane & 7;
    uint32_t a_addr[2][2], b_addr[4][2];
#pragma unroll
    for (int mf = 0; mf < 2; ++mf)
#pragma unroll
        for (int ks = 0; ks < 2; ++ks) {
            int m   = mf * 16 + rr + (g & 1) * 8;
            int seg = (g >> 1) + ks * 2;
            a_addr[mf][ks] = abase + swz(m, seg);              // AHI
        }
#pragma unroll
    for (int nf2 = 0; nf2 < 4; ++nf2)
#pragma unroll
        for (int ks = 0; ks < 2; ++ks) {
            int n   = nf2 * 16 + rr + (g >> 1) * 8;
            int seg = (g & 1) + ks * 2;
            b_addr[nf2][ks] = bbase + swz(n, seg);             // BHI
        }

    float acc[2][8][4];
#pragma unroll
    for (int mf = 0; mf < 2; ++mf)
#pragma unroll
        for (int nf = 0; nf < 8; ++nf)
#pragma unroll
            for (int r2 = 0; r2 < 4; ++r2) acc[mf][nf][r2] = 0.0f;

    const size_t kbase = (size_t)kset * 32;
    load_A(abase,           i0r,     kbase,       lane);
    load_Bhalf(bbase,       j0, ms,  kbase,       lane);
    cp_commit();
    load_A(abase + A_STAGE, i0r,     kbase + 128, lane);
    load_Bhalf(bbase + B_STAGE, j0, ms, kbase + 128, lane);
    cp_commit();

    int sRead = 0;   // B read stage  (sc % 3)
    int sFill = 2;   // B fill stage  ((sc+2) % 3)
    for (int sc = 0; sc < NSC; ++sc) {
        cp_wait<1>();                         // own halves of chunk sc complete
        bar_sync(barid, 64);                  // partner's half visible; partner
                                              // done reading stage sFill
        const uint32_t soA = (uint32_t)(sc & 1) * A_STAGE;
        const uint32_t soB = (uint32_t)sRead * B_STAGE;
        const size_t knext = kbase + (size_t)(sc + 2) * 128;
        const bool pre = (sc + 2 < NSC);

        // B refill first — overlaps the ldsm head (targets stage sFill,
        // disjoint from sRead and the in-flight (sc+1)%3 stage)
        if (pre)
            load_Bhalf(bbase + (uint32_t)sFill * B_STAGE, j0, ms, knext, lane);

        // batched ldsm (R8-proven order), both ks
        uint32_t ah[2][2][4], al[2][2][4], bh[2][4][4], bl[2][4][4];
#pragma unroll
        for (int ks = 0; ks < 2; ++ks) {
            ldsm4(ah[ks][0], a_addr[0][ks] + soA);
            ldsm4(ah[ks][1], a_addr[1][ks] + soA);
            ldsm4(al[ks][0], a_addr[0][ks] + soA + 2048);
            ldsm4(al[ks][1], a_addr[1][ks] + soA + 2048);
#pragma unroll
            for (int nf2 = 0; nf2 < 4; ++nf2) {
                ldsm4(bh[ks][nf2], b_addr[nf2][ks] + soB);
                ldsm4(bl[ks][nf2], b_addr[nf2][ks] + soB + 4096);
            }
        }

        // A refill (private; own reads of this stage all issued above)
        if (pre)
            load_A(abase + soA, i0r, knext, lane);
        cp_commit();

#pragma unroll
        for (int ks = 0; ks < 2; ++ks) {
            // hh chain
#pragma unroll
            for (int mf = 0; mf < 2; ++mf)
#pragma unroll
                for (int nf = 0; nf < 8; ++nf)
                    mma_bf16(acc[mf][nf], ah[ks][mf],
                             bh[ks][nf >> 1][(nf & 1) * 2],
                             bh[ks][nf >> 1][(nf & 1) * 2 + 1]);
            // hl chain
#pragma unroll
            for (int mf = 0; mf < 2; ++mf)
#pragma unroll
                for (int nf = 0; nf < 8; ++nf)
                    mma_bf16(acc[mf][nf], ah[ks][mf],
                             bl[ks][nf >> 1][(nf & 1) * 2],
                             bl[ks][nf >> 1][(nf & 1) * 2 + 1]);
            // lh chain
#pragma unroll
            for (int mf = 0; mf < 2; ++mf)
#pragma unroll
                for (int nf = 0; nf < 8; ++nf)
                    mma_bf16(acc[mf][nf], al[ks][mf],
                             bh[ks][nf >> 1][(nf & 1) * 2],
                             bh[ks][nf >> 1][(nf & 1) * 2 + 1]);
        }

        sRead = (sRead == 2) ? 0 : sRead + 1;
        sFill = (sFill == 2) ? 0 : sFill + 1;
    }

    // ---- epilogue: 4-set reduction + write (tile, mirror, fused diag) ----
    __syncthreads();                          // all warps done with bufs
    const int r0   = lane >> 2;
    const int cpos = (lane & 3) * 2;
    float (*sdiag)[64] = (float (*)[64])(smem + SDIAG_OFF);

    if (diagTile) {                           // per-column sums of E_cos_sq
        const int c  = tid & 63;
        const int gq = tid >> 6;              // 0..3
        float s = 0.0f;
#pragma unroll 8
        for (int p = gq * 64; p < gq * 64 + 64; ++p)
            s += g_dpart[p * KQ + j0 + c];
        sdiag[gq][c] = s;
    }

    if (kset >= 1) {
        float (*red)[RED_STRIDE] =
            (float (*)[RED_STRIDE])(smem + (size_t)(kset - 1) * RED_BYTES);
#pragma unroll
        for (int mf = 0; mf < 2; ++mf)
#pragma unroll
            for (int nf = 0; nf < 8; ++nf) {
                const int rl = wm + mf * 16 + r0;
                const int cl = nf * 8 + cpos;
                red[rl][cl]         = acc[mf][nf][0];
                red[rl][cl + 1]     = acc[mf][nf][1];
                red[rl + 8][cl]     = acc[mf][nf][2];
                red[rl + 8][cl + 1] = acc[mf][nf][3];
            }
    }
    __syncthreads();

    if (kset == 0) {
        float* __restrict__ G = out + EPHI_SZ;
        float (*red0)[RED_STRIDE] = (float (*)[RED_STRIDE])(smem);
        float (*red1)[RED_STRIDE] = (float (*)[RED_STRIDE])(smem + RED_BYTES);
        float (*red2)[RED_STRIDE] = (float (*)[RED_STRIDE])(smem + 2 * RED_BYTES);
#pragma unroll
        for (int mf = 0; mf < 2; ++mf)
#pragma unroll
            for (int nf = 0; nf < 8; ++nf)
#pragma unroll
                for (int r2 = 0; r2 < 4; ++r2) {
                    const int rl = wm + mf * 16 + r0 + (r2 >> 1) * 8;
                    const int cl = nf * 8 + cpos + (r2 & 1);
                    const int gi = i0 + rl;
                    const int gj = j0 + cl;
                    float val = acc[mf][nf][r2]
                              + red0[rl][cl] + red1[rl][cl] + red2[rl][cl];
                    if (diagTile && gi == gj)
                        val = sdiag[0][cl] + sdiag[1][cl]
                            + sdiag[2][cl] + sdiag[3][cl];
                    G[(size_t)gi * KQ + gj] = val;
                    G[(size_t)gj * KQ + gi] = val;
                }
    }
}

// ---------------------------------------------------------------------------
extern "C" void kernel_launch(void* const* d_in, const int* in_sizes, int n_in,
                              void* d_out, int out_size)
{
    const float* X           = (const float*)d_in[0];
    const float* z           = (const float*)d_in[1];
    const float* weight      = (const float*)d_in[2];
    const float* mu          = (const float*)d_in[3];
    const float* stdv        = (const float*)d_in[4];
    const float* alpha       = (const float*)d_in[5];
    const float* var_mu_w    = (const float*)d_in[6];
    const float* var_sigma_w = (const float*)d_in[7];
    float* out = (float*)d_out;

    cudaFuncSetAttribute(syrk_mma_kernel,
                         cudaFuncAttributeMaxDynamicSharedMemorySize, SMEM_SYRK);

    dim3 egrid(KQ / 256, N_PTS / 32);
    ephi_kernel<<<egrid, 256>>>(X, z, weight, mu, stdv, alpha,
                                var_mu_w, var_sigma_w, out);

    syrk_mma_kernel<<<136, 256, SMEM_SYRK>>>(out);
}